// round 4
// baseline (speedup 1.0000x reference)
#include <cuda_runtime.h>
#include <cuda_bf16.h>

#define NUM_REL   20000
#define NUM_EDGES 640000
#define DIM       128
#define NUM_HEAD  8
#define DIM_HID   16
#define NUM_BIN   10
#define NEG       0.2f
#define CAP       256   // per-relation shared cache for edge ids/tails

// ---------------- device scratch (static: no allocs allowed) ----------------
__device__ float g_P1[NUM_REL * DIM];     // emb @ W1^T + b_attn
__device__ float g_P2[NUM_REL * DIM];     // emb @ W2^T
__device__ float g_M [NUM_REL * DIM];     // emb @ Waggr^T + b_aggr
__device__ float g_attn[NUM_EDGES * NUM_HEAD];  // raw attention logits
__device__ float g_Wt1[DIM * DIM];        // transposed weights [k][j]
__device__ float g_Wt2[DIM * DIM];
__device__ float g_Wt3[DIM * DIM];
__device__ int   g_cnt[NUM_REL];
__device__ int   g_off[NUM_REL + 1];
__device__ int   g_cur[NUM_REL];
__device__ int   g_sorted[NUM_EDGES];

// ---------------- sort-by-head: zero / histogram / scan / scatter ----------------
__global__ void K_zero() {
    int i = blockIdx.x * blockDim.x + threadIdx.x;
    if (i < NUM_REL) g_cnt[i] = 0;
}

__global__ void K_hist(const int* __restrict__ trip) {
    int e = blockIdx.x * blockDim.x + threadIdx.x;
    if (e < NUM_EDGES) {
        int h = trip[e * 3];
        atomicAdd(&g_cnt[h], 1);
    }
}

__global__ void K_scan() {   // 1 block, 1024 threads
    __shared__ int part[1024];
    int tid = threadIdx.x;
    const int CH = 20;       // 1024*20 >= 20000
    int base = tid * CH;
    int s = 0;
    for (int j = 0; j < CH; j++) {
        int idx = base + j;
        if (idx < NUM_REL) s += g_cnt[idx];
    }
    part[tid] = s;
    __syncthreads();
    for (int off = 1; off < 1024; off <<= 1) {
        int v = (tid >= off) ? part[tid - off] : 0;
        __syncthreads();
        part[tid] += v;
        __syncthreads();
    }
    int run = (tid > 0) ? part[tid - 1] : 0;
    for (int j = 0; j < CH; j++) {
        int idx = base + j;
        if (idx < NUM_REL) {
            g_off[idx] = run;
            g_cur[idx] = run;
            run += g_cnt[idx];
        }
    }
    if (tid == 0) g_off[NUM_REL] = part[1023];
}

__global__ void K_scatter(const int* __restrict__ trip) {
    int e = blockIdx.x * blockDim.x + threadIdx.x;
    if (e < NUM_EDGES) {
        int h = trip[e * 3];
        int pos = atomicAdd(&g_cur[h], 1);
        g_sorted[pos] = e;
    }
}

// ---------------- weight transpose (once per launch; tiny) ----------------
__global__ void K_trans(const float* __restrict__ attn_w, const float* __restrict__ aggr_w) {
    int id = blockIdx.x * blockDim.x + threadIdx.x;
    if (id >= 3 * DIM * DIM) return;
    int mtx = id / (DIM * DIM);
    int rem = id % (DIM * DIM);
    int j = rem / DIM, k = rem % DIM;
    if (mtx == 0)       g_Wt1[k * DIM + j] = attn_w[j * (2 * DIM) + k];
    else if (mtx == 1)  g_Wt2[k * DIM + j] = attn_w[j * (2 * DIM) + DIM + k];
    else                g_Wt3[k * DIM + j] = aggr_w[j * DIM + k];
}

// ---------------- 20000x128x128 SGEMM: out[r][j] = sum_k emb[r][k]*Wt[k][j] (+bias) --------
__global__ void K_gemm(const float* __restrict__ emb, const float* __restrict__ bias, int which) {
    const float* __restrict__ Wt = (which == 0) ? g_Wt1 : (which == 1) ? g_Wt2 : g_Wt3;
    float*       __restrict__ op = (which == 0) ? g_P1  : (which == 1) ? g_P2  : g_M;

    __shared__ float embS[32 * 128];
    __shared__ float WtS[32 * 132];   // [k_local][j] padded row 132 -> conflict-free LDS.128

    int tid = threadIdx.x;
    int rbase = blockIdx.x * 32;

    const float4* eg = (const float4*)(emb + (size_t)rbase * DIM);
#pragma unroll
    for (int i = 0; i < 4; i++)
        ((float4*)embS)[tid + i * 256] = eg[tid + i * 256];

    int jt = tid & 31, j0 = jt * 4;
    int rt = tid >> 5, r0 = rt * 4;

    float acc[4][4];
#pragma unroll
    for (int a = 0; a < 4; a++)
#pragma unroll
        for (int b = 0; b < 4; b++) acc[a][b] = 0.f;

    for (int kc = 0; kc < 4; kc++) {
        __syncthreads();
#pragma unroll
        for (int i = 0; i < 4; i++) {
            int v = tid + i * 256;
            int kl = v >> 5, jq = v & 31;
            *(float4*)&WtS[kl * 132 + jq * 4] = ((const float4*)Wt)[kc * 1024 + v];
        }
        __syncthreads();
#pragma unroll
        for (int kk = 0; kk < 32; kk++) {
            int k = kc * 32 + kk;
            float4 wv = *(float4*)&WtS[kk * 132 + j0];
            float e0 = embS[(r0 + 0) * 128 + k];
            float e1 = embS[(r0 + 1) * 128 + k];
            float e2 = embS[(r0 + 2) * 128 + k];
            float e3 = embS[(r0 + 3) * 128 + k];
            acc[0][0] = fmaf(e0, wv.x, acc[0][0]); acc[0][1] = fmaf(e0, wv.y, acc[0][1]);
            acc[0][2] = fmaf(e0, wv.z, acc[0][2]); acc[0][3] = fmaf(e0, wv.w, acc[0][3]);
            acc[1][0] = fmaf(e1, wv.x, acc[1][0]); acc[1][1] = fmaf(e1, wv.y, acc[1][1]);
            acc[1][2] = fmaf(e1, wv.z, acc[1][2]); acc[1][3] = fmaf(e1, wv.w, acc[1][3]);
            acc[2][0] = fmaf(e2, wv.x, acc[2][0]); acc[2][1] = fmaf(e2, wv.y, acc[2][1]);
            acc[2][2] = fmaf(e2, wv.z, acc[2][2]); acc[2][3] = fmaf(e2, wv.w, acc[2][3]);
            acc[3][0] = fmaf(e3, wv.x, acc[3][0]); acc[3][1] = fmaf(e3, wv.y, acc[3][1]);
            acc[3][2] = fmaf(e3, wv.z, acc[3][2]); acc[3][3] = fmaf(e3, wv.w, acc[3][3]);
        }
    }

    float4 bv = make_float4(0.f, 0.f, 0.f, 0.f);
    if (bias) bv = *(const float4*)(bias + j0);
#pragma unroll
    for (int a = 0; a < 4; a++) {
        float4 o;
        o.x = acc[a][0] + bv.x; o.y = acc[a][1] + bv.y;
        o.z = acc[a][2] + bv.z; o.w = acc[a][3] + bv.w;
        *(float4*)&op[(size_t)(rbase + r0 + a) * DIM + j0] = o;
    }
}

// ---------------- fused per-relation: score + online softmax + aggregate ----------------
__global__ void K_main(const int* __restrict__ trip,
                       const float* __restrict__ attn_bin,
                       const float* __restrict__ attn_vec,
                       float* __restrict__ out) {
    __shared__ float P1s[128];
    __shared__ float vecS[128];
    __shared__ float binS[NUM_BIN * NUM_HEAD];
    __shared__ int   eS[CAP];
    __shared__ int   tailS[CAP];
    __shared__ float wM[8 * 8], wS[8 * 8];
    __shared__ float mF[8], invS[8];
    __shared__ float accS[256];

    int r = blockIdx.x;
    int tid = threadIdx.x;
    int start = g_off[r];
    int cnt = g_off[r + 1] - start;

    if (cnt == 0) {
        if (tid < 128) out[r * 128 + tid] = 0.f;
        return;
    }

    if (tid < 128) {
        P1s[tid]  = g_P1[r * 128 + tid];
        vecS[tid] = attn_vec[tid];
    }
    if (tid < NUM_BIN * NUM_HEAD) {
        float b = attn_bin[tid];
        binS[tid] = (b >= 0.f) ? b : NEG * b;
    }
    __syncthreads();

    int w = tid >> 5, lane = tid & 31;
    float m = -3.0e38f, s = 0.f;

    for (int i = w; i < cnt; i += 8) {
        int e = g_sorted[start + i];
        int tail = trip[e * 3 + 1];
        int bin  = trip[e * 3 + 2];
        float4 p2 = *(const float4*)(g_P2 + tail * 128 + lane * 4);
        float4 p1 = *(const float4*)(P1s + lane * 4);
        float4 v  = *(const float4*)(vecS + lane * 4);
        float x0 = p1.x + p2.x; x0 = (x0 >= 0.f) ? x0 : NEG * x0;
        float x1 = p1.y + p2.y; x1 = (x1 >= 0.f) ? x1 : NEG * x1;
        float x2 = p1.z + p2.z; x2 = (x2 >= 0.f) ? x2 : NEG * x2;
        float x3 = p1.w + p2.w; x3 = (x3 >= 0.f) ? x3 : NEG * x3;
        float part = x0 * v.x + x1 * v.y + x2 * v.z + x3 * v.w;
        part += __shfl_xor_sync(0xffffffffu, part, 1);
        part += __shfl_xor_sync(0xffffffffu, part, 2);
        float score = part + binS[bin * 8 + (lane >> 2)];
        if ((lane & 3) == 0) {           // one lane per head: online softmax state
            float mo = m;
            m = fmaxf(m, score);
            s = s * __expf(mo - m) + __expf(score - m);
        }
        float sc = __shfl_sync(0xffffffffu, score, (lane * 4) & 31);
        if (lane < 8) g_attn[e * 8 + lane] = sc;
        if (lane == 0 && i < CAP) { eS[i] = e; tailS[i] = tail; }
    }
    if ((lane & 3) == 0) {
        wM[w * 8 + (lane >> 2)] = m;
        wS[w * 8 + (lane >> 2)] = s;
    }
    __syncthreads();

    if (tid < 8) {
        float M = -3.0e38f;
#pragma unroll
        for (int ww = 0; ww < 8; ww++) M = fmaxf(M, wM[ww * 8 + tid]);
        float S = 0.f;
#pragma unroll
        for (int ww = 0; ww < 8; ww++) S += wS[ww * 8 + tid] * __expf(wM[ww * 8 + tid] - M);
        mF[tid] = M;
        invS[tid] = 1.f / (S + 1e-16f);
    }
    __syncthreads();

    int half = tid >> 7;     // 0/1: edges interleaved
    int d = tid & 127;
    int h = d >> 4;
    float mh = mF[h], iv = invS[h];
    float acc = 0.f;
    for (int i = half; i < cnt; i += 2) {
        int e, tail;
        if (i < CAP) { e = eS[i]; tail = tailS[i]; }
        else { e = g_sorted[start + i]; tail = trip[e * 3 + 1]; }
        float raw = g_attn[e * 8 + h];
        float beta = __expf(raw - mh) * iv;
        acc = fmaf(beta, g_M[tail * 128 + d], acc);
    }
    accS[tid] = acc;
    __syncthreads();
    if (tid < 128) out[r * 128 + tid] = accS[tid] + accS[tid + 128];
}

// ---------------- launch ----------------
extern "C" void kernel_launch(void* const* d_in, const int* in_sizes, int n_in,
                              void* d_out, int out_size) {
    const float* emb  = (const float*)d_in[0];
    const int*   trip = (const int*)d_in[1];
    const float* apw  = (const float*)d_in[2];
    const float* apb  = (const float*)d_in[3];
    const float* abin = (const float*)d_in[4];
    const float* avec = (const float*)d_in[5];
    const float* agw  = (const float*)d_in[6];
    const float* agb  = (const float*)d_in[7];
    float* out = (float*)d_out;

    K_zero<<<(NUM_REL + 255) / 256, 256>>>();
    K_trans<<<(3 * DIM * DIM + 255) / 256, 256>>>(apw, agw);
    K_gemm<<<NUM_REL / 32, 256>>>(emb, apb, 0);        // P1 (+attn bias)
    K_gemm<<<NUM_REL / 32, 256>>>(emb, nullptr, 1);    // P2
    K_gemm<<<NUM_REL / 32, 256>>>(emb, agb, 2);        // M  (+aggr bias)
    K_hist<<<(NUM_EDGES + 255) / 256, 256>>>(trip);
    K_scan<<<1, 1024>>>();
    K_scatter<<<(NUM_EDGES + 255) / 256, 256>>>(trip);
    K_main<<<NUM_REL, 256>>>(trip, abin, avec, out);
}